// round 7
// baseline (speedup 1.0000x reference)
#include <cuda_runtime.h>
#include <cuda_bf16.h>
#include <cstdint>
#include <math.h>

#define BATCH 2
#define SEQ   2048
#define HID   4096
#define NH    32
#define NKV   8
#define HD    128
#define GQA   4
#define MTOT  (BATCH*SEQ)
#define NQK   6144
#define K_DIM 4096

// GEMM v2: K-chunk 32, 3-stage pipeline, 2 CTAs/SM
#define NK2   128              // 4096/32 chunks
#define T2    8192             // 128 rows x 64 bytes
#define STG2  (4*T2)           // 32768 (Ah,Al,Bh,Bl)
#define NST   3
#define GEMM_SMEM (1024 + NST*STG2)

// attention tiles (rows: 128 bf16 + 8 pad = 272 bytes)
#define ROWB   272
#define QTILE  (128*ROWB)
#define KTILE  (64*ROWB)
#define KVBUF  (4*KTILE)
#define ATTN_SMEM (2*QTILE + 2*KVBUF)

#define QSC (0.08838834764831845f * 1.44269504088896340736f)

// ---------------- scratch ----------------
__device__ __nv_bfloat16 g_qh[(size_t)BATCH*NH*SEQ*HD],  g_ql[(size_t)BATCH*NH*SEQ*HD];
__device__ __nv_bfloat16 g_kh[(size_t)BATCH*NKV*SEQ*HD], g_kl[(size_t)BATCH*NKV*SEQ*HD];
__device__ __nv_bfloat16 g_vh[(size_t)BATCH*NKV*SEQ*HD], g_vl[(size_t)BATCH*NKV*SEQ*HD];

__device__ __nv_bfloat16 g_xh[(size_t)MTOT*HID],  g_xl[(size_t)MTOT*HID];
__device__ __nv_bfloat16 g_wh[(size_t)NQK*HID],   g_wl[(size_t)NQK*HID];
__device__ __nv_bfloat16 g_woh[(size_t)HID*HID],  g_wol[(size_t)HID*HID];
__device__ __nv_bfloat16 g_ah[(size_t)MTOT*HID],  g_al[(size_t)MTOT*HID];

// ---------------- helpers ----------------
__device__ __forceinline__ uint32_t smem_u32(const void* p){
    uint32_t a;
    asm("{ .reg .u64 t; cvta.to.shared.u64 t, %1; cvt.u32.u64 %0, t; }" : "=r"(a) : "l"(p));
    return a;
}
__device__ __forceinline__ uint32_t swz(uint32_t o){ return o ^ ((o >> 3) & 0x70); }
__device__ __forceinline__ void cp16(uint32_t d, const void* s){
    asm volatile("cp.async.cg.shared.global [%0], [%1], 16;" :: "r"(d), "l"(s));
}
__device__ __forceinline__ void cp_commit(){ asm volatile("cp.async.commit_group;" ::: "memory"); }
__device__ __forceinline__ void cp_wait0(){ asm volatile("cp.async.wait_group 0;" ::: "memory"); }
__device__ __forceinline__ void cp_wait1(){ asm volatile("cp.async.wait_group 1;" ::: "memory"); }

__device__ __forceinline__ void ldm_x4(uint32_t addr, uint32_t r[4]){
    asm volatile("ldmatrix.sync.aligned.m8n8.x4.shared.b16 {%0,%1,%2,%3}, [%4];"
                 : "=r"(r[0]), "=r"(r[1]), "=r"(r[2]), "=r"(r[3]) : "r"(addr));
}
__device__ __forceinline__ void ldm_x4_t(uint32_t addr, uint32_t r[4]){
    asm volatile("ldmatrix.sync.aligned.m8n8.x4.trans.shared.b16 {%0,%1,%2,%3}, [%4];"
                 : "=r"(r[0]), "=r"(r[1]), "=r"(r[2]), "=r"(r[3]) : "r"(addr));
}
__device__ __forceinline__ void mma_bf16(float c[4], const uint32_t a[4], const uint32_t b[2]){
    asm volatile("mma.sync.aligned.m16n8k16.row.col.f32.bf16.bf16.f32 "
                 "{%0,%1,%2,%3}, {%4,%5,%6,%7}, {%8,%9}, {%0,%1,%2,%3};"
                 : "+f"(c[0]), "+f"(c[1]), "+f"(c[2]), "+f"(c[3])
                 : "r"(a[0]), "r"(a[1]), "r"(a[2]), "r"(a[3]), "r"(b[0]), "r"(b[1]));
}
__device__ __forceinline__ float ex2f(float x){
    float y; asm("ex2.approx.ftz.f32 %0, %1;" : "=f"(y) : "f"(x)); return y;
}
__device__ __forceinline__ uint32_t splitpack(float v0, float v1, uint32_t& lo){
    uint32_t hi;
    asm("cvt.rn.bf16x2.f32 %0, %1, %2;" : "=r"(hi) : "f"(v1), "f"(v0));
    float h0 = __uint_as_float(hi << 16);
    float h1 = __uint_as_float(hi & 0xffff0000u);
    asm("cvt.rn.bf16x2.f32 %0, %1, %2;" : "=r"(lo) : "f"(v1 - h1), "f"(v0 - h0));
    return hi;
}

// ---------------- fp32 -> bf16 hi/lo split ----------------
__global__ __launch_bounds__(256) void split_kernel(
    const float* __restrict__ src, __nv_bfloat16* __restrict__ hi,
    __nv_bfloat16* __restrict__ lo, int n)
{
    int i = (blockIdx.x * 256 + threadIdx.x) * 4;
    if (i >= n) return;
    float4 v = *reinterpret_cast<const float4*>(src + i);
    float x[4] = {v.x, v.y, v.z, v.w};
    __nv_bfloat16 h[4], l[4];
#pragma unroll
    for (int j = 0; j < 4; j++) {
        h[j] = __float2bfloat16(x[j]);
        l[j] = __float2bfloat16(x[j] - __bfloat162float(h[j]));
    }
    *reinterpret_cast<uint2*>(hi + i) = *reinterpret_cast<uint2*>(h);
    *reinterpret_cast<uint2*>(lo + i) = *reinterpret_cast<uint2*>(l);
}

// ---------------- bf16x3 GEMM v2 (fragment reuse, 3-stage, 2 CTA/SM) -------
// MODE 0: QKV projection + RoPE -> bf16 hi/lo q/k/v. MODE 1: C=A@B^T -> outp.
template<int MODE>
__global__ __launch_bounds__(256, 2)
void gemm_bf16x3(
    const __nv_bfloat16* __restrict__ Ahp, const __nv_bfloat16* __restrict__ Alp,
    const __nv_bfloat16* __restrict__ Bhp, const __nv_bfloat16* __restrict__ Blp,
    const float* __restrict__ cosb, const float* __restrict__ sinb,
    float* __restrict__ outp)
{
    extern __shared__ char smem_raw[];
    const uint32_t sb = (smem_u32(smem_raw) + 1023) & ~1023u;
    const int tid = threadIdx.x;
    const int wid = tid >> 5, lane = tid & 31;
    const int m0 = blockIdx.y * 128, n0 = blockIdx.x * 128;

    const __nv_bfloat16* a_h = Ahp + (size_t)m0 * K_DIM;
    const __nv_bfloat16* a_l = Alp + (size_t)m0 * K_DIM;
    const __nv_bfloat16* b_h = Bhp + (size_t)n0 * K_DIM;
    const __nv_bfloat16* b_l = Blp + (size_t)n0 * K_DIM;

    auto load_stage = [&](int st_idx, int kc) {
        uint32_t st = sb + st_idx * STG2;
        int k0 = kc * 32;
#pragma unroll
        for (int t = 0; t < 2; t++) {
            int id = tid + t * 256;          // 0..511
            int rr = id >> 2, cc = id & 3;   // row 0..127, 16B chunk 0..3
            uint32_t off = swz(rr * 64 + cc * 16);
            size_t go = (size_t)rr * K_DIM + k0 + cc * 8;
            cp16(st + off,          a_h + go);
            cp16(st + T2 + off,     a_l + go);
            cp16(st + 2*T2 + off,   b_h + go);
            cp16(st + 3*T2 + off,   b_l + go);
        }
    };

    const int warp_m = (wid >> 2) * 64;
    const int warp_n = (wid & 3) * 32;
    const int a_off = (warp_m + (lane & 15)) * 64 + ((lane >> 4) << 4);
    const int b_off = (warp_n + (lane & 7) + ((lane & 16) >> 1)) * 64 + ((lane & 8) << 1);

    float acc[4][4][4];
#pragma unroll
    for (int mt = 0; mt < 4; mt++)
#pragma unroll
        for (int nt = 0; nt < 4; nt++)
#pragma unroll
            for (int e = 0; e < 4; e++) acc[mt][nt][e] = 0.0f;

    load_stage(0, 0); cp_commit();
    load_stage(1, 1); cp_commit();

    for (int kc = 0; kc < NK2; kc++) {
        uint32_t st = sb + (kc % NST) * STG2;
        if (kc == NK2 - 1) cp_wait0(); else cp_wait1();
        __syncthreads();

#pragma unroll
        for (int ks = 0; ks < 2; ks++) {
            uint32_t ah[4][4], al[4][4];
#pragma unroll
            for (int mt = 0; mt < 4; mt++) {
                ldm_x4(st +      swz(a_off + mt * 1024 + ks * 32), ah[mt]);
                ldm_x4(st + T2 + swz(a_off + mt * 1024 + ks * 32), al[mt]);
            }
#pragma unroll
            for (int np = 0; np < 2; np++) {
                uint32_t bh[4], bl[4];
                ldm_x4(st + 2*T2 + swz(b_off + np * 1024 + ks * 32), bh);
                ldm_x4(st + 3*T2 + swz(b_off + np * 1024 + ks * 32), bl);
#pragma unroll
                for (int mt = 0; mt < 4; mt++) {
#pragma unroll
                    for (int half = 0; half < 2; half++) {
                        float* c = acc[mt][np * 2 + half];
                        mma_bf16(c, ah[mt], bh + half * 2);
                        mma_bf16(c, al[mt], bh + half * 2);
                        mma_bf16(c, ah[mt], bl + half * 2);
                    }
                }
            }
        }
        if (kc + 2 < NK2) { load_stage((kc + 2) % NST, kc + 2); cp_commit(); }
    }

    const int g2 = lane >> 2, tg = lane & 3;
#pragma unroll
    for (int mt = 0; mt < 4; mt++) {
#pragma unroll
        for (int nt = 0; nt < 4; nt++) {
            int ct = warp_n + nt * 8 + tg * 2;
#pragma unroll
            for (int half = 0; half < 2; half++) {
                int r = warp_m + mt * 16 + g2 + half * 8;
                float c0 = acc[mt][nt][half * 2];
                float c1 = acc[mt][nt][half * 2 + 1];
                int m = m0 + r;
                if (MODE == 0) {
                    int bb = m >> 11, s = m & 2047;
                    int ng = n0 + ct;
                    __nv_bfloat16 *dh, *dl;
                    size_t idx;
                    if (ng < 4096) {
                        int hh = ng >> 7, d = ng & 127;
                        float c  = __ldg(cosb + s * HD + d);
                        float sn = __ldg(sinb + s * HD + d);
                        float o0 = c0 * c - c1 * sn;
                        float o1 = c1 * c + c0 * sn;
                        c0 = o0 * QSC; c1 = o1 * QSC;
                        idx = (((size_t)bb * NH + hh) * SEQ + s) * HD + d;
                        dh = g_qh; dl = g_ql;
                    } else if (ng < 5120) {
                        int hh = (ng - 4096) >> 7, d = ng & 127;
                        float c  = __ldg(cosb + s * HD + d);
                        float sn = __ldg(sinb + s * HD + d);
                        float o0 = c0 * c - c1 * sn;
                        float o1 = c1 * c + c0 * sn;
                        c0 = o0; c1 = o1;
                        idx = (((size_t)bb * NKV + hh) * SEQ + s) * HD + d;
                        dh = g_kh; dl = g_kl;
                    } else {
                        int hh = (ng - 5120) >> 7, d = ng & 127;
                        idx = (((size_t)bb * NKV + hh) * SEQ + s) * HD + d;
                        dh = g_vh; dl = g_vl;
                    }
                    uint32_t lo, hi = splitpack(c0, c1, lo);
                    *reinterpret_cast<uint32_t*>(dh + idx) = hi;
                    *reinterpret_cast<uint32_t*>(dl + idx) = lo;
                } else {
                    *reinterpret_cast<float2*>(outp + (size_t)m * HID + n0 + ct) =
                        make_float2(c0, c1);
                }
            }
        }
    }
}

// ---------------- mma.sync bf16 flash attention (Q fragments in registers) --
__global__ __launch_bounds__(256, 1) void attn_mma_kernel()
{
    extern __shared__ char smem_raw[];
    const uint32_t SQH = smem_u32(smem_raw);
    const uint32_t SQL = SQH + QTILE;
    const uint32_t SKV = SQL + QTILE;

    const int tid = threadIdx.x, wid = tid >> 5, lane = tid & 31;
    const int g = lane >> 2, tg = lane & 3;
    const int q0 = blockIdx.x * 128;
    const int h  = blockIdx.y;
    const int b  = blockIdx.z;
    const int kvh = h >> 2;

    const char* qh = (const char*)(g_qh + (((size_t)b * NH  + h)   * SEQ + q0) * HD);
    const char* ql = (const char*)(g_ql + (((size_t)b * NH  + h)   * SEQ + q0) * HD);
    const char* kh = (const char*)(g_kh + (((size_t)b * NKV + kvh) * SEQ) * HD);
    const char* kl = (const char*)(g_kl + (((size_t)b * NKV + kvh) * SEQ) * HD);
    const char* vh = (const char*)(g_vh + (((size_t)b * NKV + kvh) * SEQ) * HD);
    const char* vl = (const char*)(g_vl + (((size_t)b * NKV + kvh) * SEQ) * HD);

    auto load_kv = [&](int buf, int k0) {
        uint32_t base = SKV + buf * KVBUF;
#pragma unroll
        for (int t = 0; t < 4; t++) {
            int id = tid + t * 256;
            int r  = id >> 4, c = id & 15;
            size_t go = (size_t)(k0 + r) * 256 + c * 16;
            uint32_t so = r * ROWB + c * 16;
            cp16(base + so,             kh + go);
            cp16(base + KTILE + so,     kl + go);
            cp16(base + 2*KTILE + so,   vh + go);
            cp16(base + 3*KTILE + so,   vl + go);
        }
    };

#pragma unroll
    for (int t = 0; t < 8; t++) {
        int id = tid + t * 256;
        int r  = id >> 4, c = id & 15;
        size_t go = (size_t)r * 256 + c * 16;
        uint32_t so = r * ROWB + c * 16;
        cp16(SQH + so, qh + go);
        cp16(SQL + so, ql + go);
    }
    load_kv(0, 0);
    cp_commit();

    float o[16][4];
#pragma unroll
    for (int nt = 0; nt < 16; nt++)
#pragma unroll
        for (int e = 0; e < 4; e++) o[nt][e] = 0.0f;
    float m0r = -1e30f, m1r = -1e30f, l0 = 0.0f, l1 = 0.0f;

    const int qi0 = q0 + wid * 16 + g;
    const int nblk = q0 / 64 + 2;

    // wait for Q + KV0, then hoist Q fragments into registers (loop-invariant)
    cp_wait0();
    __syncthreads();
    uint32_t qfh[8][4], qfl[8][4];
#pragma unroll
    for (int ks = 0; ks < 8; ks++) {
        uint32_t qrow = SQH + (wid * 16 + (lane & 15)) * ROWB + ((lane >> 4) << 4) + ks * 32;
        ldm_x4(qrow, qfh[ks]);
        ldm_x4(qrow + QTILE, qfl[ks]);
    }

    for (int kb = 0; kb < nblk; kb++) {
        const int k0 = kb * 64;
        if (kb > 0) { cp_wait0(); __syncthreads(); }
        const uint32_t KB = SKV + (kb & 1) * KVBUF;
        if (kb + 1 < nblk) { load_kv((kb + 1) & 1, (kb + 1) * 64); cp_commit(); }

        // ---- scores: 3-term QK^T ----
        float sc[8][4];
#pragma unroll
        for (int nt = 0; nt < 8; nt++)
#pragma unroll
            for (int e = 0; e < 4; e++) sc[nt][e] = 0.0f;

#pragma unroll
        for (int ks = 0; ks < 8; ks++) {
#pragma unroll
            for (int np = 0; np < 4; np++) {
                uint32_t kaddr = KB + (np * 16 + (lane & 7) + ((lane & 16) >> 1)) * ROWB
                               + ((lane & 8) << 1) + ks * 32;
                uint32_t bh[4], bl[4];
                ldm_x4(kaddr, bh);
                ldm_x4(kaddr + KTILE, bl);
                mma_bf16(sc[2*np],   qfh[ks], bh);     mma_bf16(sc[2*np],   qfl[ks], bh);
                mma_bf16(sc[2*np],   qfh[ks], bl);
                mma_bf16(sc[2*np+1], qfh[ks], bh + 2); mma_bf16(sc[2*np+1], qfl[ks], bh + 2);
                mma_bf16(sc[2*np+1], qfh[ks], bl + 2);
            }
        }

        // ---- causal mask ----
        if (k0 + 63 > q0) {
#pragma unroll
            for (int nt = 0; nt < 8; nt++) {
                int kc = k0 + nt * 8 + tg * 2;
                if (kc     > qi0)     sc[nt][0] = -1e30f;
                if (kc + 1 > qi0)     sc[nt][1] = -1e30f;
                if (kc     > qi0 + 8) sc[nt][2] = -1e30f;
                if (kc + 1 > qi0 + 8) sc[nt][3] = -1e30f;
            }
        }

        // ---- online softmax (base-2) ----
        float mx0 = -1e30f, mx1 = -1e30f;
#pragma unroll
        for (int nt = 0; nt < 8; nt++) {
            mx0 = fmaxf(mx0, fmaxf(sc[nt][0], sc[nt][1]));
            mx1 = fmaxf(mx1, fmaxf(sc[nt][2], sc[nt][3]));
        }
        mx0 = fmaxf(mx0, __shfl_xor_sync(0xffffffffu, mx0, 1));
        mx0 = fmaxf(mx0, __shfl_xor_sync(0xffffffffu, mx0, 2));
        mx1 = fmaxf(mx1, __shfl_xor_sync(0xffffffffu, mx1, 1));
        mx1 = fmaxf(mx1, __shfl_xor_sync(0xffffffffu, mx1, 2));
        float nm0 = fmaxf(m0r, mx0), nm1 = fmaxf(m1r, mx1);
        float a0 = ex2f(m0r - nm0),  a1 = ex2f(m1r - nm1);
        m0r = nm0; m1r = nm1;
        l0 *= a0; l1 *= a1;
#pragma unroll
        for (int nt = 0; nt < 16; nt++) {
            o[nt][0] *= a0; o[nt][1] *= a0; o[nt][2] *= a1; o[nt][3] *= a1;
        }
#pragma unroll
        for (int nt = 0; nt < 8; nt++) {
            float p0 = ex2f(sc[nt][0] - nm0);
            float p1 = ex2f(sc[nt][1] - nm0);
            float p2 = ex2f(sc[nt][2] - nm1);
            float p3 = ex2f(sc[nt][3] - nm1);
            sc[nt][0] = p0; sc[nt][1] = p1; sc[nt][2] = p2; sc[nt][3] = p3;
            l0 += p0 + p1; l1 += p2 + p3;
        }

        // ---- PV: 3-term ----
#pragma unroll
        for (int j = 0; j < 4; j++) {
            uint32_t aH[4], aL[4];
            aH[0] = splitpack(sc[2*j][0],   sc[2*j][1],   aL[0]);
            aH[1] = splitpack(sc[2*j][2],   sc[2*j][3],   aL[1]);
            aH[2] = splitpack(sc[2*j+1][0], sc[2*j+1][1], aL[2]);
            aH[3] = splitpack(sc[2*j+1][2], sc[2*j+1][3], aL[3]);
#pragma unroll
            for (int nb = 0; nb < 8; nb++) {
                uint32_t vaddr = KB + 2*KTILE + (j * 16 + (lane & 15)) * ROWB
                               + ((nb * 16 + ((lane >> 4) << 3)) << 1);
                uint32_t vhf[4], vlf[4];
                ldm_x4_t(vaddr, vhf);
                ldm_x4_t(vaddr + KTILE, vlf);
                mma_bf16(o[2*nb],   aH, vhf);     mma_bf16(o[2*nb],   aL, vhf);
                mma_bf16(o[2*nb],   aH, vlf);
                mma_bf16(o[2*nb+1], aH, vhf + 2); mma_bf16(o[2*nb+1], aL, vhf + 2);
                mma_bf16(o[2*nb+1], aH, vlf + 2);
            }
        }
    }

    // ---- finalize ----
    l0 += __shfl_xor_sync(0xffffffffu, l0, 1);
    l0 += __shfl_xor_sync(0xffffffffu, l0, 2);
    l1 += __shfl_xor_sync(0xffffffffu, l1, 1);
    l1 += __shfl_xor_sync(0xffffffffu, l1, 2);
    float inv0 = 1.0f / l0, inv1 = 1.0f / l1;

    size_t row0 = ((size_t)b * SEQ + qi0)     * HID + h * 128;
    size_t row1 = ((size_t)b * SEQ + qi0 + 8) * HID + h * 128;
#pragma unroll
    for (int nt = 0; nt < 16; nt++) {
        int ct = nt * 8 + tg * 2;
        uint32_t lo, hi;
        hi = splitpack(o[nt][0] * inv0, o[nt][1] * inv0, lo);
        *reinterpret_cast<uint32_t*>(g_ah + row0 + ct) = hi;
        *reinterpret_cast<uint32_t*>(g_al + row0 + ct) = lo;
        hi = splitpack(o[nt][2] * inv1, o[nt][3] * inv1, lo);
        *reinterpret_cast<uint32_t*>(g_ah + row1 + ct) = hi;
        *reinterpret_cast<uint32_t*>(g_al + row1 + ct) = lo;
    }
}

// ---------------------------------------------------------------------------
extern "C" void kernel_launch(void* const* d_in, const int* in_sizes, int n_in,
                              void* d_out, int out_size)
{
    const float* hidden = (const float*)d_in[0];
    const float* cosb   = (const float*)d_in[1];
    const float* sinb   = (const float*)d_in[2];
    const float* wq     = (const float*)d_in[3];
    const float* wk     = (const float*)d_in[4];
    const float* wv     = (const float*)d_in[5];
    const float* wo     = (const float*)d_in[6];
    float* out = (float*)d_out;

    __nv_bfloat16 *xh, *xl, *wh, *wl, *woh, *wol, *ah, *al;
    cudaGetSymbolAddress((void**)&xh,  g_xh);  cudaGetSymbolAddress((void**)&xl,  g_xl);
    cudaGetSymbolAddress((void**)&wh,  g_wh);  cudaGetSymbolAddress((void**)&wl,  g_wl);
    cudaGetSymbolAddress((void**)&woh, g_woh); cudaGetSymbolAddress((void**)&wol, g_wol);
    cudaGetSymbolAddress((void**)&ah,  g_ah);  cudaGetSymbolAddress((void**)&al,  g_al);

    auto blocks = [](size_t n){ return (unsigned)((n / 4 + 255) / 256); };

    split_kernel<<<blocks((size_t)MTOT*HID), 256>>>(hidden, xh, xl, MTOT*HID);
    split_kernel<<<blocks((size_t)4096*4096), 256>>>(wq, wh, wl, 4096*4096);
    split_kernel<<<blocks((size_t)1024*4096), 256>>>(wk, wh + (size_t)4096*4096,
                                                     wl + (size_t)4096*4096, 1024*4096);
    split_kernel<<<blocks((size_t)1024*4096), 256>>>(wv, wh + (size_t)5120*4096,
                                                     wl + (size_t)5120*4096, 1024*4096);
    split_kernel<<<blocks((size_t)HID*HID), 256>>>(wo, woh, wol, HID*HID);

    cudaFuncSetAttribute(gemm_bf16x3<0>, cudaFuncAttributeMaxDynamicSharedMemorySize, GEMM_SMEM);
    cudaFuncSetAttribute(gemm_bf16x3<1>, cudaFuncAttributeMaxDynamicSharedMemorySize, GEMM_SMEM);

    gemm_bf16x3<0><<<dim3(48, 32), 256, GEMM_SMEM>>>(xh, xl, wh, wl, cosb, sinb, nullptr);

    cudaFuncSetAttribute(attn_mma_kernel, cudaFuncAttributeMaxDynamicSharedMemorySize, ATTN_SMEM);
    attn_mma_kernel<<<dim3(SEQ/128, NH, BATCH), 256, ATTN_SMEM>>>();

    gemm_bf16x3<1><<<dim3(32, 32), 256, GEMM_SMEM>>>(ah, al, woh, wol, nullptr, nullptr, out);
}